// round 16
// baseline (speedup 1.0000x reference)
#include <cuda_runtime.h>
#include <cuda_fp16.h>
#include <cstdint>

#define DD 256        // feature/hidden dim
#define GD 768        // 3*DD gate dim
#define LL 96         // max group length
#define TG 28         // groups per block
#define BMAX 2048
#define NT 512        // 16 warps
#define WCHUNK 3072   // bytes per warp-chunk (ring stage size)
#define WSTAGES 9216  // 3 stages x 3072 per warp
#define OPW 260       // halves per h-operand row (256 + 4 pad)

// ---- main-kernel smem layout (bytes) ----
#define OFF_W    0                    // [16 warps][3 stages][3072] = 147456
#define OFF_H0H  147456               // [32][OPW] half = 16640
#define OFF_H1H  164096               // 16640
#define OFF_SR   180736               // [256][TG] half = 14336 (xp_r staging)
#define OFF_SZ   195072               // [256][TG] half (xp_z staging / z out)
#define OFF_SN   209408               // [256][TG] half (xp_n staging / n out)
#define OFF_CB   223744               // [2][768] float combined biases
#define OFF_HB   229888               // [2][256] float hh n-bias
#define SMEM_TOT 231936

// ---- xp precompute kernel smem ----
#define XSTG     1536
#define XP_RING  73728                // 16 x 3 x 1536
#define XP_SMEM  (XP_RING + 64 * OPW * 2)

typedef unsigned int u32;

// ---------------- device scratch ----------------
__device__ int    g_order[BMAX * LL];   // edge id per (group,t), -1 = pad
// blob A: [layer][warp][chunk16][mat][gate3][row16][16h], k16 XOR swizzle baked
__device__ __half g_wblob[786432];
// blob B: W_hh0 [warp][chunk8(k32)][gate3][row16][32h], k32 XOR swizzle baked
__device__ __half g_whh0[196608];
// precomputed xp = W_ih0 @ x (no bias), [e][768] fp16
__device__ __half g_xp[(size_t)BMAX * LL * GD];

// ---------------- helpers ----------------
__device__ __forceinline__ float sigmoidf_(float v) {
    return __fdividef(1.f, 1.f + __expf(-v));
}
__device__ __forceinline__ float tanhf_(float v) {
    float t = __expf(2.f * v);
    return 1.f - __fdividef(2.f, t + 1.f);
}
__device__ __forceinline__ void cpc16(u32 dst, const void* src) {
    asm volatile("cp.async.cg.shared.global [%0], [%1], 16;\n" :: "r"(dst), "l"(src));
}
#define CPA_COMMIT() asm volatile("cp.async.commit_group;\n" ::)
#define CPA_WAIT2()  asm volatile("cp.async.wait_group 2;\n" ::: "memory")

__device__ __forceinline__ void ldsm_x4(u32& r0, u32& r1, u32& r2, u32& r3, u32 addr) {
    asm volatile("ldmatrix.sync.aligned.m8n8.x4.shared.b16 {%0,%1,%2,%3}, [%4];"
                 : "=r"(r0), "=r"(r1), "=r"(r2), "=r"(r3) : "r"(addr));
}
__device__ __forceinline__ void mma16(float* c, u32 a0, u32 a1, u32 a2, u32 a3,
                                      u32 b0, u32 b1) {
    asm volatile("mma.sync.aligned.m16n8k16.row.col.f32.f16.f16.f32 "
                 "{%0,%1,%2,%3}, {%4,%5,%6,%7}, {%8,%9}, {%0,%1,%2,%3};"
                 : "+f"(c[0]), "+f"(c[1]), "+f"(c[2]), "+f"(c[3])
                 : "r"(a0), "r"(a1), "r"(a2), "r"(a3), "r"(b0), "r"(b1));
}

// ---------------- fused setup: group sort + both weight blobs ----------------
__global__ void setup_k(const float* __restrict__ ts, const int* __restrict__ index,
                        int E, int B,
                        const float* __restrict__ wih0, const float* __restrict__ whh0,
                        const float* __restrict__ wih1, const float* __restrict__ whh1)
{
    const int b = blockIdx.x;
    if (b < B) {
        __shared__ int   lbub[2];
        __shared__ float sts[LL];
        const int i = threadIdx.x;
        if (i < 2) {
            const int key = b + i;
            int lo = 0, hi = E;
            while (lo < hi) {
                int m = (lo + hi) >> 1;
                if (index[m] < key) lo = m + 1; else hi = m;
            }
            lbub[i] = lo;
        }
        __syncthreads();
        const int off = lbub[0];
        const int c   = lbub[1] - lbub[0];
        if (i < c)  sts[i] = ts[off + i];
        if (i < LL) g_order[b * LL + i] = -1;
        __syncthreads();
        if (i < c) {
            const float ti = sts[i];
            int rank = 0;
            for (int j = 0; j < c; ++j) {
                float tj = sts[j];
                rank += (tj < ti || (tj == ti && j < i)) ? 1 : 0;
            }
            g_order[b * LL + (LL - c + rank)] = off + i;
        }
    } else {
        int idx = (b - B) * 256 + threadIdx.x;       // 0 .. 983039
        if (idx < 786432) {
            // blob A: [p][wp][c16][m][g][row16][hp16]
            int p   = idx / 393216;  int r1 = idx % 393216;
            int wp  = r1 / 24576;    int r2 = r1 % 24576;
            int c   = r2 / 1536;     int r3 = r2 % 1536;
            int m   = r3 / 768;      int r4 = r3 % 768;
            int g   = r4 / 256;      int r5 = r4 % 256;
            int row16 = r5 / 16;     int hp = r5 % 16;
            int us  = hp >> 3;       int k8 = hp & 7;
            int ul  = us ^ ((row16 >> 2) & 1);
            int k   = c * 16 + ul * 8 + k8;
            int row = g * 256 + wp * 16 + row16;
            const float* W = (p == 0) ? (m == 0 ? wih0 : whh0)
                                      : (m == 0 ? wih1 : whh1);
            g_wblob[idx] = __float2half_rn(W[row * DD + k]);
        } else if (idx < 983040) {
            // blob B: W_hh0 [wp][c8][g][row16][hp32]
            int i2 = idx - 786432;
            int wp = i2 / 12288;     int r1 = i2 % 12288;
            int c  = r1 / 1536;      int r2 = r1 % 1536;
            int g  = r2 / 512;       int r3 = r2 % 512;
            int row16 = r3 / 32;     int hp = r3 % 32;
            int us = hp >> 3;        int k8 = hp & 7;
            int ul = us ^ ((row16 >> 1) & 3);
            int k  = c * 32 + ul * 8 + k8;
            int row = g * 256 + wp * 16 + row16;
            g_whh0[i2] = __float2half_rn(whh0[row * DD + k]);
        }
    }
}

// ---------------- xp precompute: xp[e][768] = W_ih0 @ x[e] ----------------
__global__ __launch_bounds__(NT, 1) void xp_k(const float* __restrict__ x, int E)
{
    extern __shared__ char sb[];
    __half* xt = (__half*)(sb + XP_RING);            // [64][OPW]
    const int tid  = threadIdx.x;
    const int w    = tid >> 5;
    const int lane = tid & 31;
    const int e0   = blockIdx.x * 64;

    const u32 wstw = (u32)__cvta_generic_to_shared(sb) + (u32)(w * 3 * XSTG);
    const char* wsrc = (const char*)g_wblob + (size_t)w * 49152;   // layer0, warp w

    for (int idx = tid; idx < 64 * DD; idx += NT) {
        const int r = idx >> 8, c = idx & 255;
        const int e = e0 + r;
        xt[r * OPW + c] = (e < E) ? __float2half_rn(x[(size_t)e * DD + c]) : __half(0.f);
    }
    __syncthreads();

    float acc[96];
#pragma unroll
    for (int i = 0; i < 96; ++i) acc[i] = 0.f;

    const int loff = lane * 16;
    {
        const char* s0 = wsrc + 0 * WCHUNK + loff;
        const char* s1 = wsrc + 1 * WCHUNK + loff;
        u32 d0 = wstw + 0 * XSTG + loff, d1 = wstw + 1 * XSTG + loff;
        cpc16(d0, s0); cpc16(d0 + 512, s0 + 512); cpc16(d0 + 1024, s0 + 1024);
        CPA_COMMIT();
        cpc16(d1, s1); cpc16(d1 + 512, s1 + 512); cpc16(d1 + 1024, s1 + 1024);
        CPA_COMMIT();
    }

    const int rowl = lane & 15;
    const u32 axor = (u32)((((lane >> 4) ^ ((rowl >> 2) & 1))) * 16);

#pragma unroll 1
    for (int i = 0; i < 16; ++i) {
        if (i + 2 < 16) {
            const char* s = wsrc + (i + 2) * WCHUNK + loff;
            u32 d = wstw + ((i + 2) % 3) * XSTG + loff;
            cpc16(d, s); cpc16(d + 512, s + 512); cpc16(d + 1024, s + 1024);
        }
        CPA_COMMIT();
        CPA_WAIT2();
        const u32 sbase = wstw + (i % 3) * XSTG;
        const int kh = i * 16;
        u32 a[3][4];
#pragma unroll
        for (int j = 0; j < 3; ++j)
            ldsm_x4(a[j][0], a[j][1], a[j][2], a[j][3],
                    sbase + (u32)(j * 512 + rowl * 32) + axor);
#pragma unroll
        for (int nt = 0; nt < 8; ++nt) {
            const int brow = (nt * 8 + (lane >> 2)) * OPW + (lane & 3) * 2 + kh;
            const u32 b0 = *(const u32*)(xt + brow);
            const u32 b1 = *(const u32*)(xt + brow + 8);
#pragma unroll
            for (int j = 0; j < 3; ++j)
                mma16(&acc[(j * 8 + nt) * 4], a[j][0], a[j][1], a[j][2], a[j][3], b0, b1);
        }
    }

    const int r0 = lane >> 2, cp2 = (lane & 3) * 2;
#pragma unroll
    for (int j = 0; j < 3; ++j) {
        const int d0 = j * 256 + w * 16 + r0;     // gate-aligned ownership
#pragma unroll
        for (int nt = 0; nt < 8; ++nt) {
            const int e = e0 + nt * 8 + cp2;
            const float* c = &acc[(j * 8 + nt) * 4];
            if (e < E) {
                g_xp[(size_t)e * GD + d0]     = __float2half_rn(c[0]);
                g_xp[(size_t)e * GD + d0 + 8] = __float2half_rn(c[2]);
            }
            if (e + 1 < E) {
                g_xp[(size_t)(e + 1) * GD + d0]     = __float2half_rn(c[1]);
                g_xp[(size_t)(e + 1) * GD + d0 + 8] = __float2half_rn(c[3]);
            }
        }
    }
}

// ---------------- per-warp 3072B chunk copy ----------------
__device__ __forceinline__ void issue_chunk(const char* __restrict__ wsrc, int c,
                                            u32 wstw, int stage, int loff) {
    const char* s = wsrc + c * WCHUNK + loff;
    u32 dst = wstw + stage * WCHUNK + loff;
#pragma unroll
    for (int q = 0; q < 6; ++q) cpc16(dst + q * 512, s + q * 512);
}

// ---------------- xp gather into gate arrays (transposed [d][g]) ----------------
__device__ __forceinline__ void gather_xp(__half* s_r, __half* s_z, __half* s_n,
                                          int g0, int B, int t, int tid)
{
#pragma unroll 1
    for (int q = tid; q < 96 * TG; q += NT) {
        const int g = q / 96, off = q % 96;
        const int grp = g0 + g;
        const int e = (grp < B) ? g_order[grp * LL + t] : -1;
        uint4 v = (e >= 0) ? *(const uint4*)(g_xp + (size_t)e * GD + off * 8)
                           : make_uint4(0, 0, 0, 0);
        const __half* hv = (const __half*)&v;
        const int k = off * 8;
        __half* dst = (k < 256) ? s_r : (k < 512) ? s_z : s_n;
        const int kk = k & 255;
#pragma unroll
        for (int j = 0; j < 8; ++j) dst[(kk + j) * TG + g] = hv[j];
    }
}

// ---------------- layer 0: hh GEMM (k32) + fused publish ----------------
__device__ __forceinline__ void pass0(
    const char* __restrict__ wsrc, const __half* __restrict__ opB,
    __half* __restrict__ s_r, __half* __restrict__ s_z, __half* __restrict__ s_n,
    const float* __restrict__ cbl, const float* __restrict__ hbl,
    u32 wstw, int w, int lane)
{
    float aR[16], aZ[16], aN[16];
#pragma unroll
    for (int i = 0; i < 16; ++i) { aR[i] = 0.f; aZ[i] = 0.f; aN[i] = 0.f; }

    const int loff = lane * 16;
    issue_chunk(wsrc, 0, wstw, 0, loff); CPA_COMMIT();
    issue_chunk(wsrc, 1, wstw, 1, loff); CPA_COMMIT();

    const int rowl = lane & 15;
    const int ksel = lane >> 4;
    const u32 sw0  = (u32)(((rowl >> 1) & 3) * 16);
    const int bof  = (lane >> 2) * OPW + (lane & 3) * 2;

#pragma unroll 1
    for (int i = 0; i < 8; ++i) {
        if (i + 2 < 8) issue_chunk(wsrc, i + 2, wstw, (i + 2) % 3, loff);
        CPA_COMMIT();
        CPA_WAIT2();
        const u32 sbase = wstw + (i % 3) * WCHUNK;
#pragma unroll
        for (int kk = 0; kk < 2; ++kk) {
            const int kh = i * 32 + kk * 16;
            u32 b0[4], b1[4];
#pragma unroll
            for (int nt = 0; nt < 4; ++nt) {
                b0[nt] = *(const u32*)(opB + nt * 8 * OPW + bof + kh);
                b1[nt] = *(const u32*)(opB + nt * 8 * OPW + bof + kh + 8);
            }
#pragma unroll
            for (int g3 = 0; g3 < 3; ++g3) {
                u32 a0, a1, a2, a3;
                const u32 addr = sbase + (u32)(g3 * 1024 + rowl * 64)
                               + ((u32)((kk * 2 + ksel) * 16) ^ sw0);
                ldsm_x4(a0, a1, a2, a3, addr);
                float* acc = (g3 == 0) ? aR : (g3 == 1) ? aZ : aN;
#pragma unroll
                for (int nt = 0; nt < 4; ++nt)
                    mma16(&acc[nt * 4], a0, a1, a2, a3, b0[nt], b1[nt]);
            }
        }
    }

    // fused publish (same warp owns r,z,n for its 16 d-rows)
    const int r0 = lane >> 2, cp2 = (lane & 3) * 2;
    const int d0 = w * 16 + r0, d1 = d0 + 8;
    const float rb0 = cbl[d0],       rb1 = cbl[d1];
    const float zb0 = cbl[256 + d0], zb1 = cbl[256 + d1];
    const float nb0 = cbl[512 + d0], nb1 = cbl[512 + d1];
    const float hv0 = hbl[d0],       hv1 = hbl[d1];
#pragma unroll
    for (int nt = 0; nt < 4; ++nt) {
        const int col = nt * 8 + cp2;
        if (col >= TG) continue;
        float2 xr0 = __half22float2(*(const __half2*)&s_r[d0 * TG + col]);
        float2 xr1 = __half22float2(*(const __half2*)&s_r[d1 * TG + col]);
        float2 xz0 = __half22float2(*(const __half2*)&s_z[d0 * TG + col]);
        float2 xz1 = __half22float2(*(const __half2*)&s_z[d1 * TG + col]);
        float2 xn0 = __half22float2(*(const __half2*)&s_n[d0 * TG + col]);
        float2 xn1 = __half22float2(*(const __half2*)&s_n[d1 * TG + col]);
        float r00 = sigmoidf_(xr0.x + aR[nt * 4 + 0] + rb0);
        float r01 = sigmoidf_(xr0.y + aR[nt * 4 + 1] + rb0);
        float r10 = sigmoidf_(xr1.x + aR[nt * 4 + 2] + rb1);
        float r11 = sigmoidf_(xr1.y + aR[nt * 4 + 3] + rb1);
        *(__half2*)&s_z[d0 * TG + col] = __floats2half2_rn(
            sigmoidf_(xz0.x + aZ[nt * 4 + 0] + zb0),
            sigmoidf_(xz0.y + aZ[nt * 4 + 1] + zb0));
        *(__half2*)&s_z[d1 * TG + col] = __floats2half2_rn(
            sigmoidf_(xz1.x + aZ[nt * 4 + 2] + zb1),
            sigmoidf_(xz1.y + aZ[nt * 4 + 3] + zb1));
        *(__half2*)&s_n[d0 * TG + col] = __floats2half2_rn(
            tanhf_(xn0.x + nb0 + r00 * (aN[nt * 4 + 0] + hv0)),
            tanhf_(xn0.y + nb0 + r01 * (aN[nt * 4 + 1] + hv0)));
        *(__half2*)&s_n[d1 * TG + col] = __floats2half2_rn(
            tanhf_(xn1.x + nb1 + r10 * (aN[nt * 4 + 2] + hv1)),
            tanhf_(xn1.y + nb1 + r11 * (aN[nt * 4 + 3] + hv1)));
    }
}

// ---------------- layer 1: 2-matrix GEMM (k16, rz-combined) + fused publish ----------------
__device__ __forceinline__ void pass1(
    const char* __restrict__ wsrc,
    const __half* __restrict__ opA, const __half* __restrict__ opB,
    __half* __restrict__ s_z, __half* __restrict__ s_n,
    const float* __restrict__ cbl, const float* __restrict__ hbl,
    u32 wstw, int w, int lane)
{
    float aRZ[32], cxN[16], chN[16];
#pragma unroll
    for (int i = 0; i < 32; ++i) aRZ[i] = 0.f;
#pragma unroll
    for (int i = 0; i < 16; ++i) { cxN[i] = 0.f; chN[i] = 0.f; }

    const int loff = lane * 16;
    issue_chunk(wsrc, 0, wstw, 0, loff); CPA_COMMIT();
    issue_chunk(wsrc, 1, wstw, 1, loff); CPA_COMMIT();

    const int rowl = lane & 15;
    const u32 axor = (u32)((((lane >> 4) ^ ((rowl >> 2) & 1))) * 16);
    const int bof  = (lane >> 2) * OPW + (lane & 3) * 2;

#pragma unroll 1
    for (int i = 0; i < 16; ++i) {
        if (i + 2 < 16) issue_chunk(wsrc, i + 2, wstw, (i + 2) % 3, loff);
        CPA_COMMIT();
        CPA_WAIT2();
        const u32 sbase = wstw + (i % 3) * WCHUNK;
        const int kh = i * 16;
        u32 p0[4], p1[4], q0[4], q1[4];
#pragma unroll
        for (int nt = 0; nt < 4; ++nt) {
            p0[nt] = *(const u32*)(opA + nt * 8 * OPW + bof + kh);
            p1[nt] = *(const u32*)(opA + nt * 8 * OPW + bof + kh + 8);
            q0[nt] = *(const u32*)(opB + nt * 8 * OPW + bof + kh);
            q1[nt] = *(const u32*)(opB + nt * 8 * OPW + bof + kh + 8);
        }
#pragma unroll
        for (int g3 = 0; g3 < 3; ++g3) {
            const u32 base = sbase + (u32)(g3 * 512 + rowl * 32) + axor;
            u32 a0, a1, a2, a3, h0, h1, h2, h3;
            ldsm_x4(a0, a1, a2, a3, base);            // W_ih1
            ldsm_x4(h0, h1, h2, h3, base + 1536);     // W_hh1
            if (g3 < 2) {
                float* acc = &aRZ[g3 * 16];
#pragma unroll
                for (int nt = 0; nt < 4; ++nt) {
                    mma16(&acc[nt * 4], a0, a1, a2, a3, p0[nt], p1[nt]);
                    mma16(&acc[nt * 4], h0, h1, h2, h3, q0[nt], q1[nt]);
                }
            } else {
#pragma unroll
                for (int nt = 0; nt < 4; ++nt) {
                    mma16(&cxN[nt * 4], a0, a1, a2, a3, p0[nt], p1[nt]);
                    mma16(&chN[nt * 4], h0, h1, h2, h3, q0[nt], q1[nt]);
                }
            }
        }
    }

    const int r0 = lane >> 2, cp2 = (lane & 3) * 2;
    const int d0 = w * 16 + r0, d1 = d0 + 8;
    const float rb0 = cbl[d0],       rb1 = cbl[d1];
    const float zb0 = cbl[256 + d0], zb1 = cbl[256 + d1];
    const float nb0 = cbl[512 + d0], nb1 = cbl[512 + d1];
    const float hv0 = hbl[d0],       hv1 = hbl[d1];
#pragma unroll
    for (int nt = 0; nt < 4; ++nt) {
        const int col = nt * 8 + cp2;
        if (col >= TG) continue;
        float r00 = sigmoidf_(aRZ[nt * 4 + 0] + rb0);
        float r01 = sigmoidf_(aRZ[nt * 4 + 1] + rb0);
        float r10 = sigmoidf_(aRZ[nt * 4 + 2] + rb1);
        float r11 = sigmoidf_(aRZ[nt * 4 + 3] + rb1);
        *(__half2*)&s_z[d0 * TG + col] = __floats2half2_rn(
            sigmoidf_(aRZ[16 + nt * 4 + 0] + zb0),
            sigmoidf_(aRZ[16 + nt * 4 + 1] + zb0));
        *(__half2*)&s_z[d1 * TG + col] = __floats2half2_rn(
            sigmoidf_(aRZ[16 + nt * 4 + 2] + zb1),
            sigmoidf_(aRZ[16 + nt * 4 + 3] + zb1));
        *(__half2*)&s_n[d0 * TG + col] = __floats2half2_rn(
            tanhf_(cxN[nt * 4 + 0] + nb0 + r00 * (chN[nt * 4 + 0] + hv0)),
            tanhf_(cxN[nt * 4 + 1] + nb0 + r01 * (chN[nt * 4 + 1] + hv0)));
        *(__half2*)&s_n[d1 * TG + col] = __floats2half2_rn(
            tanhf_(cxN[nt * 4 + 2] + nb1 + r10 * (chN[nt * 4 + 2] + hv1)),
            tanhf_(cxN[nt * 4 + 3] + nb1 + r11 * (chN[nt * 4 + 3] + hv1)));
    }
}

// ---------------- main persistent kernel ----------------
__global__ __launch_bounds__(NT, 1) void gru_main(
    const float* __restrict__ bih0, const float* __restrict__ bhh0,
    const float* __restrict__ bih1, const float* __restrict__ bhh1,
    float* __restrict__ out, int B)
{
    extern __shared__ char sb[];
    const int g0 = blockIdx.x * TG;
    if (g0 >= B) return;                 // pad blocks (grid held at >=148)

    __half* h0h = (__half*)(sb + OFF_H0H);
    __half* h1h = (__half*)(sb + OFF_H1H);
    __half* s_r = (__half*)(sb + OFF_SR);
    __half* s_z = (__half*)(sb + OFF_SZ);
    __half* s_n = (__half*)(sb + OFF_SN);
    float*  cb  = (float*)(sb + OFF_CB);
    float*  hb  = (float*)(sb + OFF_HB);

    const int tid  = threadIdx.x;
    const int w    = tid >> 5;
    const int lane = tid & 31;
    const int d    = tid & 255;
    const int gb   = tid >> 8;           // 0 or 1

    const u32 wstw = (u32)__cvta_generic_to_shared(sb + OFF_W) + (u32)(w * WSTAGES);
    const char* w0w = (const char*)g_whh0             + (size_t)w * 24576;
    const char* w1w = (const char*)(g_wblob + 393216) + (size_t)w * 49152;

    for (int i = tid; i < GD; i += NT) {
        cb[i]      = (i < 512) ? bih0[i] + bhh0[i] : bih0[i];
        cb[GD + i] = (i < 512) ? bih1[i] + bhh1[i] : bih1[i];
    }
    for (int i = tid; i < DD; i += NT) {
        hb[i]      = bhh0[512 + i];
        hb[DD + i] = bhh1[512 + i];
    }
    // zero h0h + h1h (contiguous: 2 x 16640 B = 8320 u32)
    for (int i = tid; i < 8320; i += NT) ((u32*)h0h)[i] = 0;
    __syncthreads();

    gather_xp(s_r, s_z, s_n, g0, B, 0, tid);

    float acc[14];
#pragma unroll
    for (int i = 0; i < 14; ++i) acc[i] = 0.f;
    __syncthreads();

#pragma unroll 1
    for (int t = 0; t < LL; ++t) {
        // ---- layer 0 ----
        pass0(w0w, h0h, s_r, s_z, s_n, cb, hb, wstw, w, lane);
        __syncthreads();                  // S1: z,n published
#pragma unroll
        for (int i = 0; i < 14; ++i) {
            const int g = gb + 2 * i;
            float z = __half2float(s_z[d * TG + g]);
            float n = __half2float(s_n[d * TG + g]);
            float h = __half2float(h0h[g * OPW + d]);
            h0h[g * OPW + d] = __float2half_rn(n + z * (h - n));
        }
        __syncthreads();                  // S2: h0h stable

        // ---- layer 1 ----
        pass1(w1w, h0h, h1h, s_z, s_n, cb + GD, hb + DD, wstw, w, lane);
        __syncthreads();                  // S3
#pragma unroll
        for (int i = 0; i < 14; ++i) {
            const int g = gb + 2 * i;
            float z = __half2float(s_z[d * TG + g]);
            float n = __half2float(s_n[d * TG + g]);
            float h = __half2float(h1h[g * OPW + d]);
            float hn2 = n + z * (h - n);
            h1h[g * OPW + d] = __float2half_rn(hn2);
            acc[i] += hn2;
        }
        __syncthreads();                  // S4: gate arrays free
        if (t + 1 < LL) gather_xp(s_r, s_z, s_n, g0, B, t + 1, tid);
        __syncthreads();                  // S5: xp staged
    }

#pragma unroll
    for (int i = 0; i < 14; ++i) {
        const int grp = g0 + gb + 2 * i;
        if (grp < B) out[(size_t)grp * DD + d] = acc[i] * (1.0f / LL);
    }
}

// ---------------- entry point ----------------
extern "C" void kernel_launch(void* const* d_in, const int* in_sizes, int n_in,
                              void* d_out, int out_size) {
    const float* x     = (const float*)d_in[0];
    const float* ts    = (const float*)d_in[1];
    const float* wih0  = (const float*)d_in[2];
    const float* whh0  = (const float*)d_in[3];
    const float* bih0  = (const float*)d_in[4];
    const float* bhh0  = (const float*)d_in[5];
    const float* wih1  = (const float*)d_in[6];
    const float* whh1  = (const float*)d_in[7];
    const float* bih1  = (const float*)d_in[8];
    const float* bhh1  = (const float*)d_in[9];
    const int*   index = (const int*)d_in[10];
    float* out = (float*)d_out;

    const int E = in_sizes[0] / DD;
    const int B = out_size / DD;

    cudaFuncSetAttribute(gru_main, cudaFuncAttributeMaxDynamicSharedMemorySize, SMEM_TOT);
    cudaFuncSetAttribute(xp_k, cudaFuncAttributeMaxDynamicSharedMemorySize, XP_SMEM);

    setup_k<<<B + 3840, 256>>>(ts, index, E, B, wih0, whh0, wih1, whh1);
    xp_k<<<(E + 63) / 64, NT, XP_SMEM>>>(x, E);

    int nb = (B + TG - 1) / TG;
    if (nb < 148) nb = 148;
    gru_main<<<nb, NT, SMEM_TOT>>>(bih0, bhh0, bih1, bhh1, out, B);
}